// round 1
// baseline (speedup 1.0000x reference)
#include <cuda_runtime.h>

#define BB 16
#define NN 512   // seq1 rows
#define MM 448   // seq2 rows
#define DD 1536

// cost_t[b][m][n] = ||seq1[b][n] - seq2[b][m]||  (transposed layout for JV)
__device__ float g_cost[BB * MM * NN];
__device__ float g_n1[BB * NN];
__device__ float g_n2[BB * MM];
__device__ int   g_perm[BB * NN];

// ---------------------------------------------------------------------------
// Row norms: one warp per row.
// ---------------------------------------------------------------------------
__global__ void norms_kernel(const float* __restrict__ seq1,
                             const float* __restrict__ seq2) {
    int warp = (blockIdx.x * blockDim.x + threadIdx.x) >> 5;
    int lane = threadIdx.x & 31;
    int total = BB * (NN + MM);
    if (warp >= total) return;
    const float* ptr;
    float* out;
    if (warp < BB * NN) {
        ptr = seq1 + (size_t)warp * DD;
        out = g_n1 + warp;
    } else {
        int w = warp - BB * NN;
        ptr = seq2 + (size_t)w * DD;
        out = g_n2 + w;
    }
    float s = 0.f;
    for (int k = lane * 4; k < DD; k += 32 * 4) {
        float4 v = *(const float4*)(ptr + k);
        s += v.x * v.x + v.y * v.y + v.z * v.z + v.w * v.w;
    }
#pragma unroll
    for (int o = 16; o > 0; o >>= 1) s += __shfl_down_sync(0xffffffffu, s, o);
    if (lane == 0) *out = s;
}

// ---------------------------------------------------------------------------
// Cost matrix: tiled fp32 GEMM  dot = seq2[m] . seq1[n], then sqrt epilogue.
// Tile 64(m) x 64(n) x 16(k), 256 threads, 4x4 per thread.
// ---------------------------------------------------------------------------
#define TBM 64
#define TBN 64
#define TBK 16

__global__ void __launch_bounds__(256) cost_kernel(const float* __restrict__ seq1,
                                                   const float* __restrict__ seq2) {
    __shared__ float As[TBK][TBM + 4];  // seq2 tile, k-major
    __shared__ float Bs[TBK][TBN + 4];  // seq1 tile, k-major

    int b  = blockIdx.z;
    int m0 = blockIdx.y * TBM;
    int n0 = blockIdx.x * TBN;
    const float* A  = seq2 + ((size_t)b * MM + m0) * DD;
    const float* Bp = seq1 + ((size_t)b * NN + n0) * DD;

    int tid = threadIdx.x;
    int lr  = tid >> 2;         // 0..63 : row within tile
    int lc  = (tid & 3) * 4;    // 0,4,8,12 : k offset (float4)
    int ty  = tid >> 4;         // 0..15 (m sub)
    int tx  = tid & 15;         // 0..15 (n sub)

    float acc[4][4] = {};

    for (int k0 = 0; k0 < DD; k0 += TBK) {
        float4 av = *(const float4*)(A  + (size_t)lr * DD + k0 + lc);
        float4 bv = *(const float4*)(Bp + (size_t)lr * DD + k0 + lc);
        __syncthreads();
        As[lc + 0][lr] = av.x; As[lc + 1][lr] = av.y;
        As[lc + 2][lr] = av.z; As[lc + 3][lr] = av.w;
        Bs[lc + 0][lr] = bv.x; Bs[lc + 1][lr] = bv.y;
        Bs[lc + 2][lr] = bv.z; Bs[lc + 3][lr] = bv.w;
        __syncthreads();
#pragma unroll
        for (int k = 0; k < TBK; k++) {
            float4 a = *(const float4*)&As[k][ty * 4];
            float4 bb = *(const float4*)&Bs[k][tx * 4];
            float ar[4] = {a.x, a.y, a.z, a.w};
            float br[4] = {bb.x, bb.y, bb.z, bb.w};
#pragma unroll
            for (int im = 0; im < 4; im++)
#pragma unroll
                for (int in = 0; in < 4; in++)
                    acc[im][in] += ar[im] * br[in];
        }
    }

#pragma unroll
    for (int im = 0; im < 4; im++) {
        int m = m0 + ty * 4 + im;
        float nm = g_n2[b * MM + m];
#pragma unroll
        for (int in = 0; in < 4; in++) {
            int n = n0 + tx * 4 + in;
            float d2 = nm + g_n1[b * NN + n] - 2.0f * acc[im][in];
            g_cost[((size_t)b * MM + m) * NN + n] = sqrtf(fmaxf(d2, 0.0f));
        }
    }
}

// ---------------------------------------------------------------------------
// JV (Jonker-Volgenant) rectangular assignment, exact replica of reference
// algorithm on the transposed cost (448 rows x 512 cols). One block per batch,
// 512 threads (one per column). Potentials in double to match float64 ref.
// ---------------------------------------------------------------------------
#define INFD 1e18

__global__ void __launch_bounds__(512) jv_kernel() {
    __shared__ double u[MM + 1];       // 449
    __shared__ double v[NN + 1];       // 513
    __shared__ double minv[NN + 1];
    __shared__ int    way[NN + 1];
    __shared__ int    p[NN + 1];
    __shared__ unsigned char used[NN + 1];
    __shared__ double rval[16];
    __shared__ int    ridx[16];
    __shared__ int    sh_j0, sh_i0, sh_j1, sh_free;
    __shared__ double sh_delta;

    int b = blockIdx.x;
    const float* cbase = g_cost + (size_t)b * MM * NN;
    int tid = threadIdx.x;
    int j = tid + 1;                   // this thread's column, 1..512

    // init
    p[j] = 0; v[j] = 0.0;
    if (tid < MM + 1) u[tid] = 0.0;
    if (tid == 0) { p[0] = 0; v[0] = 0.0; }
    __syncthreads();

    for (int i = 1; i <= MM; i++) {
        minv[j] = INFD; used[j] = 0;
        if (tid == 0) { minv[0] = INFD; used[0] = 0; p[0] = i; sh_j0 = 0; }
        __syncthreads();

        while (true) {
            if (tid == 0) {
                int j0 = sh_j0;
                used[j0] = 1;
                sh_i0 = p[j0];
            }
            __syncthreads();                                   // S1
            int i0 = sh_i0;
            int j0c = sh_j0;

            double best;
            if (!used[j]) {
                double cur = (double)cbase[(size_t)(i0 - 1) * NN + (j - 1)]
                             - u[i0] - v[j];
                if (cur < minv[j]) { minv[j] = cur; way[j] = j0c; }
                best = minv[j];
            } else {
                best = INFD;
            }
            int bidx = j;

            // warp-level min/argmin (ties -> lowest index, matching np.argmin)
#pragma unroll
            for (int o = 16; o > 0; o >>= 1) {
                double ov = __shfl_down_sync(0xffffffffu, best, o);
                int    oi = __shfl_down_sync(0xffffffffu, bidx, o);
                if (ov < best || (ov == best && oi < bidx)) { best = ov; bidx = oi; }
            }
            int w = tid >> 5;
            if ((tid & 31) == 0) { rval[w] = best; ridx[w] = bidx; }
            __syncthreads();                                   // S2
            if (w == 0) {
                int lane = tid & 31;
                double bv2 = (lane < 16) ? rval[lane] : INFD;
                int    bi2 = (lane < 16) ? ridx[lane] : 0x7fffffff;
#pragma unroll
                for (int o = 8; o > 0; o >>= 1) {
                    double ov = __shfl_down_sync(0xffffffffu, bv2, o);
                    int    oi = __shfl_down_sync(0xffffffffu, bi2, o);
                    if (ov < bv2 || (ov == bv2 && oi < bi2)) { bv2 = ov; bi2 = oi; }
                }
                if (lane == 0) { sh_delta = bv2; sh_j1 = bi2; sh_j0 = bi2; }
            }
            __syncthreads();                                   // S3

            double delta = sh_delta;
            if (used[j]) { u[p[j]] += delta; v[j] -= delta; }
            else         { minv[j] -= delta; }
            if (tid == 0) {
                u[p[0]] += delta;              // column 0 is always "used"
                sh_free = (p[sh_j1] == 0);
            }
            __syncthreads();                                   // S4
            if (sh_free) break;
        }

        // augment along alternating path (serial, tiny)
        if (tid == 0) {
            int j0 = sh_j1;
            while (j0 != 0) {
                int jp = way[j0];
                p[j0] = p[jp];
                j0 = jp;
            }
        }
        __syncthreads();
    }

    // perm = matched original rows ascending, then unmatched ascending
    if (tid == 0) {
        int base = b * NN;
        int k = 0;
        for (int jj = 1; jj <= NN; jj++) if (p[jj] != 0) g_perm[base + k++] = jj - 1;
        for (int jj = 1; jj <= NN; jj++) if (p[jj] == 0) g_perm[base + k++] = jj - 1;
    }
}

// ---------------------------------------------------------------------------
// Gather: out[b][k] = seq1[b][perm[b][k]]
// ---------------------------------------------------------------------------
__global__ void gather_kernel(const float* __restrict__ seq1,
                              float* __restrict__ out) {
    int b   = blockIdx.y;
    int row = blockIdx.x;
    int src = g_perm[b * NN + row];
    const float4* s = (const float4*)(seq1 + ((size_t)b * NN + src) * DD);
    float4*       d = (float4*)(out  + ((size_t)b * NN + row) * DD);
    int k = threadIdx.x;                 // 384 threads, DD/4 = 384
    d[k] = s[k];
}

// ---------------------------------------------------------------------------
extern "C" void kernel_launch(void* const* d_in, const int* in_sizes, int n_in,
                              void* d_out, int out_size) {
    const float* seq1 = (const float*)d_in[0];
    const float* seq2 = (const float*)d_in[1];
    float* out = (float*)d_out;

    int totalRows = BB * (NN + MM);                 // 15360 rows, 8 warps/block
    norms_kernel<<<totalRows / 8, 256>>>(seq1, seq2);

    dim3 gc(NN / TBN, MM / TBM, BB);                // (8, 7, 16)
    cost_kernel<<<gc, 256>>>(seq1, seq2);

    jv_kernel<<<BB, 512>>>();

    gather_kernel<<<dim3(NN, BB), DD / 4>>>(seq1, out);
}

// round 2
// speedup vs baseline: 1.3951x; 1.3951x over previous
#include <cuda_runtime.h>

#define BB 16
#define NN 512   // seq1 rows (columns of transposed cost)
#define MM 448   // seq2 rows (rows of transposed cost)
#define DD 1536
#define FULL 0xffffffffu

// cost_t[b][m][n] = ||seq1[b][n] - seq2[b][m]||  (transposed layout for JV)
__device__ float g_cost[BB * MM * NN];
__device__ float g_n1[BB * NN];
__device__ float g_n2[BB * MM];
__device__ int   g_perm[BB * NN];

// ---------------------------------------------------------------------------
// Row norms: one warp per row.
// ---------------------------------------------------------------------------
__global__ void norms_kernel(const float* __restrict__ seq1,
                             const float* __restrict__ seq2) {
    int warp = (blockIdx.x * blockDim.x + threadIdx.x) >> 5;
    int lane = threadIdx.x & 31;
    int total = BB * (NN + MM);
    if (warp >= total) return;
    const float* ptr;
    float* out;
    if (warp < BB * NN) {
        ptr = seq1 + (size_t)warp * DD;
        out = g_n1 + warp;
    } else {
        int w = warp - BB * NN;
        ptr = seq2 + (size_t)w * DD;
        out = g_n2 + w;
    }
    float s = 0.f;
    for (int k = lane * 4; k < DD; k += 32 * 4) {
        float4 v = *(const float4*)(ptr + k);
        s += v.x * v.x + v.y * v.y + v.z * v.z + v.w * v.w;
    }
#pragma unroll
    for (int o = 16; o > 0; o >>= 1) s += __shfl_down_sync(FULL, s, o);
    if (lane == 0) *out = s;
}

// ---------------------------------------------------------------------------
// Cost matrix: tiled fp32 GEMM  dot = seq2[m] . seq1[n], then sqrt epilogue.
// ---------------------------------------------------------------------------
#define TBM 64
#define TBN 64
#define TBK 16

__global__ void __launch_bounds__(256) cost_kernel(const float* __restrict__ seq1,
                                                   const float* __restrict__ seq2) {
    __shared__ float As[TBK][TBM + 4];
    __shared__ float Bs[TBK][TBN + 4];

    int b  = blockIdx.z;
    int m0 = blockIdx.y * TBM;
    int n0 = blockIdx.x * TBN;
    const float* A  = seq2 + ((size_t)b * MM + m0) * DD;
    const float* Bp = seq1 + ((size_t)b * NN + n0) * DD;

    int tid = threadIdx.x;
    int lr  = tid >> 2;
    int lc  = (tid & 3) * 4;
    int ty  = tid >> 4;
    int tx  = tid & 15;

    float acc[4][4] = {};

    for (int k0 = 0; k0 < DD; k0 += TBK) {
        float4 av = *(const float4*)(A  + (size_t)lr * DD + k0 + lc);
        float4 bv = *(const float4*)(Bp + (size_t)lr * DD + k0 + lc);
        __syncthreads();
        As[lc + 0][lr] = av.x; As[lc + 1][lr] = av.y;
        As[lc + 2][lr] = av.z; As[lc + 3][lr] = av.w;
        Bs[lc + 0][lr] = bv.x; Bs[lc + 1][lr] = bv.y;
        Bs[lc + 2][lr] = bv.z; Bs[lc + 3][lr] = bv.w;
        __syncthreads();
#pragma unroll
        for (int k = 0; k < TBK; k++) {
            float4 a  = *(const float4*)&As[k][ty * 4];
            float4 bb = *(const float4*)&Bs[k][tx * 4];
            float ar[4] = {a.x, a.y, a.z, a.w};
            float br[4] = {bb.x, bb.y, bb.z, bb.w};
#pragma unroll
            for (int im = 0; im < 4; im++)
#pragma unroll
                for (int in = 0; in < 4; in++)
                    acc[im][in] += ar[im] * br[in];
        }
    }

#pragma unroll
    for (int im = 0; im < 4; im++) {
        int m = m0 + ty * 4 + im;
        float nm = g_n2[b * MM + m];
#pragma unroll
        for (int in = 0; in < 4; in++) {
            int n = n0 + tx * 4 + in;
            float d2 = nm + g_n1[b * NN + n] - 2.0f * acc[im][in];
            g_cost[((size_t)b * MM + m) * NN + n] = sqrtf(fmaxf(d2, 0.0f));
        }
    }
}

// ---------------------------------------------------------------------------
// Warp-synchronous JV with shifted potentials. One warp per batch.
// Lane owns columns j-1 = 32*c + lane, c = 0..15.
// ---------------------------------------------------------------------------
#define MAXU64 0xFFFFFFFFFFFFFFFFULL

__device__ __forceinline__ unsigned long long dsort(double d) {
    long long x = __double_as_longlong(d);
    return (unsigned long long)(x ^ ((x >> 63) | 0x8000000000000000LL));
}
__device__ __forceinline__ double dunsort(unsigned long long u) {
    long long x = (long long)u;
    long long b = (x < 0) ? (x ^ 0x8000000000000000LL) : ~x;
    return __longlong_as_double(b);
}

__global__ void __launch_bounds__(32) jv_warp_kernel() {
    __shared__ double u[MM + 1];     // row potentials (u0 during a Dijkstra)
    __shared__ double sarr[NN];      // D at marking time, per column
    __shared__ int    p[NN + 1];     // column -> assigned row (1-based), 0 = free
    __shared__ int    way[NN + 1];

    int b = blockIdx.x;
    const float* cbase = g_cost + (size_t)b * MM * NN;
    int lane = threadIdx.x;

    for (int t = lane; t < MM + 1; t += 32) u[t] = 0.0;
    for (int t = lane; t < NN + 1; t += 32) { p[t] = 0; way[t] = 0; }
    double v[16];
#pragma unroll
    for (int c = 0; c < 16; c++) v[c] = 0.0;
    __syncwarp();

    for (int i = 1; i <= MM; i++) {
        unsigned long long msort[16];
#pragma unroll
        for (int c = 0; c < 16; c++) msort[c] = MAXU64;
        unsigned umask = 0;
        double D = 0.0;
        int i0 = i;
        int j0 = 0;
        if (lane == 0) p[0] = i;
        __syncwarp();

        int jsel;
        double Df;

        while (true) {
            double h = D - u[i0];
            const float* crow = cbase + (size_t)(i0 - 1) * NN;

            float f[16];
#pragma unroll
            for (int c = 0; c < 16; c++) f[c] = __ldg(crow + c * 32 + lane);

#pragma unroll
            for (int c = 0; c < 16; c++) {
                double cur = ((double)f[c] + h) - v[c];
                unsigned long long cs = dsort(cur);
                if (!((umask >> c) & 1u) && cs < msort[c]) {
                    msort[c] = cs;
                    way[c * 32 + lane + 1] = j0;
                }
            }

            // local min/argmin tree over 16 (left priority -> lowest c on tie)
            unsigned long long lv[8]; int lc2[8];
#pragma unroll
            for (int k = 0; k < 8; k++) {
                lv[k] = msort[2 * k]; lc2[k] = 2 * k;
                if (msort[2 * k + 1] < lv[k]) { lv[k] = msort[2 * k + 1]; lc2[k] = 2 * k + 1; }
            }
#pragma unroll
            for (int k = 0; k < 4; k++)
                if (lv[k + 4] < lv[k]) { lv[k] = lv[k + 4]; lc2[k] = lc2[k + 4]; }
#pragma unroll
            for (int k = 0; k < 2; k++)
                if (lv[k + 2] < lv[k]) { lv[k] = lv[k + 2]; lc2[k] = lc2[k + 2]; }
            if (lv[1] < lv[0]) { lv[0] = lv[1]; lc2[0] = lc2[1]; }
            unsigned long long bv = lv[0];
            int bc = lc2[0];

            // warp argmin: value via 2x REDUX, index (= j-1, exact lowest-j
            // tie-break) via a 3rd REDUX on packed 32*c+lane.
            unsigned hi = (unsigned)(bv >> 32);
            unsigned mh = __reduce_min_sync(FULL, hi);
            unsigned lo = (hi == mh) ? (unsigned)bv : 0xFFFFFFFFu;
            unsigned ml = __reduce_min_sync(FULL, lo);
            bool win = (hi == mh) && ((unsigned)bv == ml);
            unsigned key = win ? (unsigned)(bc * 32 + lane) : 0xFFFFFFFFu;
            unsigned mk = __reduce_min_sync(FULL, key);
            int j1 = (int)mk + 1;

            unsigned long long wsv = __shfl_sync(FULL, bv, (int)(mk & 31u));
            double Dnew = dunsort(wsv);
            D = Dnew;

            int pj1 = p[j1];           // broadcast LDS
            if (pj1 == 0) { jsel = j1; Df = Dnew; break; }

            // mark j1 used
            if (lane == (int)(mk & 31u)) {
                int mc = (int)(mk >> 5);
                umask |= 1u << mc;
                msort[mc] = MAXU64;
                sarr[j1 - 1] = Dnew;
            }
            i0 = pj1;
            j0 = j1;
        }

        // deferred dual updates (before augmentation; p[] is pre-augment)
        unsigned um = umask;
        while (um) {
            int c = __ffs(um) - 1; um &= um - 1;
            int j = c * 32 + lane + 1;
            double adj = Df - sarr[j - 1];
            v[c] -= adj;
            int r = p[j];              // distinct rows across all used columns
            u[r] += adj;
        }
        if (lane == 0) u[i] += Df;
        __syncwarp();

        if (lane == 0) {
            int j0a = jsel;
            while (j0a) { int jp = way[j0a]; p[j0a] = p[jp]; j0a = jp; }
        }
        __syncwarp();
    }

    // perm: matched original rows ascending, then unmatched ascending
    int mbase = b * NN, mo = 0, uo = MM;
#pragma unroll
    for (int c = 0; c < 16; c++) {
        int j = c * 32 + lane + 1;
        bool mt = (p[j] != 0);
        unsigned bal = __ballot_sync(FULL, mt);
        unsigned ltm = (lane == 0) ? 0u : (FULL >> (32 - lane));
        int lt  = __popc(bal & ltm);
        int ltu = __popc((~bal) & ltm);
        if (mt)  g_perm[mbase + mo + lt]  = j - 1;
        if (!mt) g_perm[mbase + uo + ltu] = j - 1;
        mo += __popc(bal);
        uo += 32 - __popc(bal);
    }
}

// ---------------------------------------------------------------------------
// Gather: out[b][k] = seq1[b][perm[b][k]]
// ---------------------------------------------------------------------------
__global__ void gather_kernel(const float* __restrict__ seq1,
                              float* __restrict__ out) {
    int b   = blockIdx.y;
    int row = blockIdx.x;
    int src = g_perm[b * NN + row];
    const float4* s = (const float4*)(seq1 + ((size_t)b * NN + src) * DD);
    float4*       d = (float4*)(out  + ((size_t)b * NN + row) * DD);
    int k = threadIdx.x;
    d[k] = s[k];
}

// ---------------------------------------------------------------------------
extern "C" void kernel_launch(void* const* d_in, const int* in_sizes, int n_in,
                              void* d_out, int out_size) {
    const float* seq1 = (const float*)d_in[0];
    const float* seq2 = (const float*)d_in[1];
    float* out = (float*)d_out;

    int totalRows = BB * (NN + MM);
    norms_kernel<<<totalRows / 8, 256>>>(seq1, seq2);

    dim3 gc(NN / TBN, MM / TBM, BB);
    cost_kernel<<<gc, 256>>>(seq1, seq2);

    jv_warp_kernel<<<BB, 32>>>();

    gather_kernel<<<dim3(NN, BB), DD / 4>>>(seq1, out);
}

// round 3
// speedup vs baseline: 1.6562x; 1.1872x over previous
#include <cuda_runtime.h>

#define BB 16
#define NN 512   // seq1 rows (columns of transposed cost)
#define MM 448   // seq2 rows (rows of transposed cost)
#define DD 1536
#define FULL 0xffffffffu

// cost_t[b][m][n] = ||seq1[b][n] - seq2[b][m]||  (transposed layout for JV)
__device__ float g_cost[BB * MM * NN];
__device__ float g_n1[BB * NN];
__device__ float g_n2[BB * MM];
__device__ int   g_perm[BB * NN];

// ---------------------------------------------------------------------------
// Row norms: one warp per row.
// ---------------------------------------------------------------------------
__global__ void norms_kernel(const float* __restrict__ seq1,
                             const float* __restrict__ seq2) {
    int warp = (blockIdx.x * blockDim.x + threadIdx.x) >> 5;
    int lane = threadIdx.x & 31;
    int total = BB * (NN + MM);
    if (warp >= total) return;
    const float* ptr;
    float* out;
    if (warp < BB * NN) {
        ptr = seq1 + (size_t)warp * DD;
        out = g_n1 + warp;
    } else {
        int w = warp - BB * NN;
        ptr = seq2 + (size_t)w * DD;
        out = g_n2 + w;
    }
    float s = 0.f;
    for (int k = lane * 4; k < DD; k += 32 * 4) {
        float4 v = *(const float4*)(ptr + k);
        s += v.x * v.x + v.y * v.y + v.z * v.z + v.w * v.w;
    }
#pragma unroll
    for (int o = 16; o > 0; o >>= 1) s += __shfl_down_sync(FULL, s, o);
    if (lane == 0) *out = s;
}

// ---------------------------------------------------------------------------
// Cost matrix: tiled fp32 GEMM  dot = seq2[m] . seq1[n], then sqrt epilogue.
// ---------------------------------------------------------------------------
#define TBM 64
#define TBN 64
#define TBK 16

__global__ void __launch_bounds__(256) cost_kernel(const float* __restrict__ seq1,
                                                   const float* __restrict__ seq2) {
    __shared__ float As[TBK][TBM + 4];
    __shared__ float Bs[TBK][TBN + 4];

    int b  = blockIdx.z;
    int m0 = blockIdx.y * TBM;
    int n0 = blockIdx.x * TBN;
    const float* A  = seq2 + ((size_t)b * MM + m0) * DD;
    const float* Bp = seq1 + ((size_t)b * NN + n0) * DD;

    int tid = threadIdx.x;
    int lr  = tid >> 2;
    int lc  = (tid & 3) * 4;
    int ty  = tid >> 4;
    int tx  = tid & 15;

    float acc[4][4] = {};

    for (int k0 = 0; k0 < DD; k0 += TBK) {
        float4 av = *(const float4*)(A  + (size_t)lr * DD + k0 + lc);
        float4 bv = *(const float4*)(Bp + (size_t)lr * DD + k0 + lc);
        __syncthreads();
        As[lc + 0][lr] = av.x; As[lc + 1][lr] = av.y;
        As[lc + 2][lr] = av.z; As[lc + 3][lr] = av.w;
        Bs[lc + 0][lr] = bv.x; Bs[lc + 1][lr] = bv.y;
        Bs[lc + 2][lr] = bv.z; Bs[lc + 3][lr] = bv.w;
        __syncthreads();
#pragma unroll
        for (int k = 0; k < TBK; k++) {
            float4 a  = *(const float4*)&As[k][ty * 4];
            float4 bb = *(const float4*)&Bs[k][tx * 4];
            float ar[4] = {a.x, a.y, a.z, a.w};
            float br[4] = {bb.x, bb.y, bb.z, bb.w};
#pragma unroll
            for (int im = 0; im < 4; im++)
#pragma unroll
                for (int in = 0; in < 4; in++)
                    acc[im][in] += ar[im] * br[in];
        }
    }

#pragma unroll
    for (int im = 0; im < 4; im++) {
        int m = m0 + ty * 4 + im;
        float nm = g_n2[b * MM + m];
#pragma unroll
        for (int in = 0; in < 4; in++) {
            int n = n0 + tx * 4 + in;
            float d2 = nm + g_n1[b * NN + n] - 2.0f * acc[im][in];
            g_cost[((size_t)b * MM + m) * NN + n] = sqrtf(fmaxf(d2, 0.0f));
        }
    }
}

// ---------------------------------------------------------------------------
// Warp-synchronous JV with shifted potentials + fp32 filter / fp64 fallback.
// One warp per batch. Lane owns columns j-1 = 32*c + lane, c = 0..15.
// ---------------------------------------------------------------------------
#define MAXU64 0xFFFFFFFFFFFFFFFFULL
#define GUARD  1e-3f

__device__ __forceinline__ unsigned long long dsort(double d) {
    long long x = __double_as_longlong(d);
    return (unsigned long long)(x ^ ((x >> 63) | 0x8000000000000000LL));
}
__device__ __forceinline__ double dunsort(unsigned long long u) {
    long long x = (long long)u;
    long long b = (x < 0) ? (x ^ 0x8000000000000000LL) : ~x;
    return __longlong_as_double(b);
}

__global__ void __launch_bounds__(32) jv_warp_kernel() {
    __shared__ double u[MM + 1];     // row potentials (frozen during a Dijkstra)
    __shared__ double sarr[NN];      // D at marking time, per column
    __shared__ int    p[NN + 1];     // column -> assigned row (1-based), 0 = free
    __shared__ int    way[NN + 1];

    int b = blockIdx.x;
    const float* cbase = g_cost + (size_t)b * MM * NN;
    int lane = threadIdx.x;

    for (int t = lane; t < MM + 1; t += 32) u[t] = 0.0;
    for (int t = lane; t < NN + 1; t += 32) { p[t] = 0; way[t] = 0; }
    double v[16];
    float  vf[16];
#pragma unroll
    for (int c = 0; c < 16; c++) { v[c] = 0.0; vf[c] = 0.0f; }
    __syncwarp();

    for (int i = 1; i <= MM; i++) {
        unsigned long long msort[16];   // exact sorted-bits of minv
        float minvf[16];                // fp32 approx of minv (filter key)
#pragma unroll
        for (int c = 0; c < 16; c++) { msort[c] = MAXU64; minvf[c] = 3.0e38f; }
        unsigned long long lmin = MAXU64;   // lane-local min over unused cols
        int lidx = 0;
        unsigned umask = 0;
        double D = 0.0;
        int i0 = i;
        int j0 = 0;
        if (lane == 0) p[0] = i;
        __syncwarp();

        int jsel;
        double Df;

        while (true) {
            double h = D - u[i0];
            float hf = (float)h;
            const float* crow = cbase + (size_t)(i0 - 1) * NN;

            float f[16];
#pragma unroll
            for (int c = 0; c < 16; c++) f[c] = __ldg(crow + c * 32 + lane);

            // fp32 filter: which columns might improve? (guard >> rounding err)
            unsigned pmask = 0;
#pragma unroll
            for (int c = 0; c < 16; c++) {
                float curf = (f[c] - vf[c]) + hf;
                if (curf < minvf[c] + GUARD) pmask |= 1u << c;
            }

            // exact fp64 updates only for filtered columns
            while (pmask) {
                int c = __ffs(pmask) - 1;
                pmask &= pmask - 1;
                double cur = ((double)f[c] + h) - v[c];
                unsigned long long cs = dsort(cur);
                if (cs < msort[c]) {
                    msort[c] = cs;
                    minvf[c] = (float)cur;
                    way[c * 32 + lane + 1] = j0;
                    if (cs < lmin) { lmin = cs; lidx = c; }
                }
            }

            // warp argmin: exact value via 2x REDUX on sorted bits, index
            // (= j-1, exact lowest-j tie-break) via 3rd REDUX on 32*c+lane.
            unsigned hi = (unsigned)(lmin >> 32);
            unsigned mh = __reduce_min_sync(FULL, hi);
            unsigned lo = (hi == mh) ? (unsigned)lmin : 0xFFFFFFFFu;
            unsigned ml = __reduce_min_sync(FULL, lo);
            bool win = (hi == mh) && ((unsigned)lmin == ml);
            unsigned key = win ? (unsigned)(lidx * 32 + lane) : 0xFFFFFFFFu;
            unsigned mk = __reduce_min_sync(FULL, key);
            int j1 = (int)mk + 1;

            unsigned long long wsv = __shfl_sync(FULL, lmin, (int)(mk & 31u));
            double Dnew = dunsort(wsv);
            D = Dnew;

            int pj1 = p[j1];           // broadcast LDS
            if (pj1 == 0) { jsel = j1; Df = Dnew; break; }

            // mark j1 used (winner lane only) + rebuild its local min
            if (lane == (int)(mk & 31u)) {
                int mc = (int)(mk >> 5);
                umask |= 1u << mc;
                msort[mc] = MAXU64;
                minvf[mc] = -3.0e38f;   // filter can never pass again
                sarr[j1 - 1] = Dnew;
                lmin = MAXU64; lidx = 0;
#pragma unroll
                for (int c2 = 0; c2 < 16; c2++)
                    if (msort[c2] < lmin) { lmin = msort[c2]; lidx = c2; }
            }
            i0 = pj1;
            j0 = j1;
        }

        // deferred dual updates (before augmentation; p[] is pre-augment)
        unsigned um = umask;
        while (um) {
            int c = __ffs(um) - 1; um &= um - 1;
            int j = c * 32 + lane + 1;
            double adj = Df - sarr[j - 1];
            v[c] -= adj;
            vf[c] = (float)v[c];
            int r = p[j];              // distinct rows across all used columns
            u[r] += adj;
        }
        if (lane == 0) u[i] += Df;
        __syncwarp();

        if (lane == 0) {
            int j0a = jsel;
            while (j0a) { int jp = way[j0a]; p[j0a] = p[jp]; j0a = jp; }
        }
        __syncwarp();
    }

    // perm: matched original rows ascending, then unmatched ascending
    int mbase = b * NN, mo = 0, uo = MM;
#pragma unroll
    for (int c = 0; c < 16; c++) {
        int j = c * 32 + lane + 1;
        bool mt = (p[j] != 0);
        unsigned bal = __ballot_sync(FULL, mt);
        unsigned ltm = (lane == 0) ? 0u : (FULL >> (32 - lane));
        int lt  = __popc(bal & ltm);
        int ltu = __popc((~bal) & ltm);
        if (mt)  g_perm[mbase + mo + lt]  = j - 1;
        if (!mt) g_perm[mbase + uo + ltu] = j - 1;
        mo += __popc(bal);
        uo += 32 - __popc(bal);
    }
}

// ---------------------------------------------------------------------------
// Gather: out[b][k] = seq1[b][perm[b][k]]
// ---------------------------------------------------------------------------
__global__ void gather_kernel(const float* __restrict__ seq1,
                              float* __restrict__ out) {
    int b   = blockIdx.y;
    int row = blockIdx.x;
    int src = g_perm[b * NN + row];
    const float4* s = (const float4*)(seq1 + ((size_t)b * NN + src) * DD);
    float4*       d = (float4*)(out  + ((size_t)b * NN + row) * DD);
    int k = threadIdx.x;
    d[k] = s[k];
}

// ---------------------------------------------------------------------------
extern "C" void kernel_launch(void* const* d_in, const int* in_sizes, int n_in,
                              void* d_out, int out_size) {
    const float* seq1 = (const float*)d_in[0];
    const float* seq2 = (const float*)d_in[1];
    float* out = (float*)d_out;

    int totalRows = BB * (NN + MM);
    norms_kernel<<<totalRows / 8, 256>>>(seq1, seq2);

    dim3 gc(NN / TBN, MM / TBM, BB);
    cost_kernel<<<gc, 256>>>(seq1, seq2);

    jv_warp_kernel<<<BB, 32>>>();

    gather_kernel<<<dim3(NN, BB), DD / 4>>>(seq1, out);
}

// round 8
// speedup vs baseline: 1.8170x; 1.0971x over previous
#include <cuda_runtime.h>

#define BB 16
#define NN 512   // seq1 rows (columns of transposed cost)
#define MM 448   // seq2 rows (rows of transposed cost)
#define DD 1536
#define FULL 0xffffffffu

// cost_t[b][m][n] = ||seq1[b][n] - seq2[b][m]||  (transposed layout for JV)
__device__ float g_cost[BB * MM * NN];
__device__ float g_n1[BB * NN];
__device__ float g_n2[BB * MM];
__device__ int   g_perm[BB * NN];

// ---------------------------------------------------------------------------
// Row norms: one warp per row.
// ---------------------------------------------------------------------------
__global__ void norms_kernel(const float* __restrict__ seq1,
                             const float* __restrict__ seq2) {
    int warp = (blockIdx.x * blockDim.x + threadIdx.x) >> 5;
    int lane = threadIdx.x & 31;
    int total = BB * (NN + MM);
    if (warp >= total) return;
    const float* ptr;
    float* out;
    if (warp < BB * NN) {
        ptr = seq1 + (size_t)warp * DD;
        out = g_n1 + warp;
    } else {
        int w = warp - BB * NN;
        ptr = seq2 + (size_t)w * DD;
        out = g_n2 + w;
    }
    float s = 0.f;
    for (int k = lane * 4; k < DD; k += 32 * 4) {
        float4 v = *(const float4*)(ptr + k);
        s += v.x * v.x + v.y * v.y + v.z * v.z + v.w * v.w;
    }
#pragma unroll
    for (int o = 16; o > 0; o >>= 1) s += __shfl_down_sync(FULL, s, o);
    if (lane == 0) *out = s;
}

// ---------------------------------------------------------------------------
// Cost matrix: tiled fp32 GEMM  dot = seq2[m] . seq1[n], then sqrt epilogue.
// ---------------------------------------------------------------------------
#define TBM 64
#define TBN 64
#define TBK 16

__global__ void __launch_bounds__(256) cost_kernel(const float* __restrict__ seq1,
                                                   const float* __restrict__ seq2) {
    __shared__ float As[TBK][TBM + 4];
    __shared__ float Bs[TBK][TBN + 4];

    int b  = blockIdx.z;
    int m0 = blockIdx.y * TBM;
    int n0 = blockIdx.x * TBN;
    const float* A  = seq2 + ((size_t)b * MM + m0) * DD;
    const float* Bp = seq1 + ((size_t)b * NN + n0) * DD;

    int tid = threadIdx.x;
    int lr  = tid >> 2;
    int lc  = (tid & 3) * 4;
    int ty  = tid >> 4;
    int tx  = tid & 15;

    float acc[4][4] = {};

    for (int k0 = 0; k0 < DD; k0 += TBK) {
        float4 av = *(const float4*)(A  + (size_t)lr * DD + k0 + lc);
        float4 bv = *(const float4*)(Bp + (size_t)lr * DD + k0 + lc);
        __syncthreads();
        As[lc + 0][lr] = av.x; As[lc + 1][lr] = av.y;
        As[lc + 2][lr] = av.z; As[lc + 3][lr] = av.w;
        Bs[lc + 0][lr] = bv.x; Bs[lc + 1][lr] = bv.y;
        Bs[lc + 2][lr] = bv.z; Bs[lc + 3][lr] = bv.w;
        __syncthreads();
#pragma unroll
        for (int k = 0; k < TBK; k++) {
            float4 a  = *(const float4*)&As[k][ty * 4];
            float4 bb = *(const float4*)&Bs[k][tx * 4];
            float ar[4] = {a.x, a.y, a.z, a.w};
            float br[4] = {bb.x, bb.y, bb.z, bb.w};
#pragma unroll
            for (int im = 0; im < 4; im++)
#pragma unroll
                for (int in = 0; in < 4; in++)
                    acc[im][in] += ar[im] * br[in];
        }
    }

#pragma unroll
    for (int im = 0; im < 4; im++) {
        int m = m0 + ty * 4 + im;
        float nm = g_n2[b * MM + m];
#pragma unroll
        for (int in = 0; in < 4; in++) {
            int n = n0 + tx * 4 + in;
            float d2 = nm + g_n1[b * NN + n] - 2.0f * acc[im][in];
            g_cost[((size_t)b * MM + m) * NN + n] = sqrtf(fmaxf(d2, 0.0f));
        }
    }
}

// ---------------------------------------------------------------------------
// LAP via row reduction + greedy tight seeding + exact Dijkstra (SSP).
// Duals: u[i] = min_j c[i][j], v = 0  -> feasible, and v stays 0 on ALL free
// columns forever (only matched columns receive v updates), which is the
// invariant that makes terminal free-column selection by reduced distance
// equivalent to real-cost selection (u[i] is a common offset).
// One warp per batch; lane owns columns j-1 = 32*c + lane, c = 0..15.
// ---------------------------------------------------------------------------
#define MAXU64 0xFFFFFFFFFFFFFFFFULL
#define GUARD  1e-3f

__device__ __forceinline__ unsigned long long dsort(double d) {
    long long x = __double_as_longlong(d);
    return (unsigned long long)(x ^ ((x >> 63) | 0x8000000000000000LL));
}
__device__ __forceinline__ double dunsort(unsigned long long u) {
    long long x = (long long)u;
    long long b = (x < 0) ? (x ^ 0x8000000000000000LL) : ~x;
    return __longlong_as_double(b);
}

__global__ void __launch_bounds__(32) jv_warp_kernel() {
    __shared__ double u[MM + 1];     // row potentials (init: row minima)
    __shared__ double sarr[NN];      // D at marking time, per column
    __shared__ int    p[NN + 1];     // column -> assigned row (1-based), 0=free
    __shared__ int    way[NN + 1];
    __shared__ int    argcol[MM + 1];// row -> argmin column (1-based)
    __shared__ int    freelist[MM];

    int b = blockIdx.x;
    const float* cbase = g_cost + (size_t)b * MM * NN;
    int lane = threadIdx.x;

    for (int t = lane; t < NN + 1; t += 32) { p[t] = 0; way[t] = 0; }
    __syncwarp();

    // ---- Phase A: row reduction  u[i] = min_j c[i][j], record argmin -----
    for (int i = 1; i <= MM; i++) {
        const float* crow = cbase + (size_t)(i - 1) * NN;
        float m = 3.0e38f;
        int bj = 0x7fffffff;
#pragma unroll
        for (int c = 0; c < 16; c++) {
            float f = __ldg(crow + c * 32 + lane);
            if (f < m) { m = f; bj = c * 32 + lane; }
        }
#pragma unroll
        for (int o = 16; o > 0; o >>= 1) {
            float om = __shfl_xor_sync(FULL, m, o);
            int obj = __shfl_xor_sync(FULL, bj, o);
            if (om < m || (om == m && obj < bj)) { m = om; bj = obj; }
        }
        if (lane == 0) { u[i] = (double)m; argcol[i] = bj + 1; }
    }
    __syncwarp();

    // ---- Phase B: greedy tight seeding (lane 0, serial) ------------------
    int numfree = 0;
    if (lane == 0) {
        for (int i = 1; i <= MM; i++) {
            int j = argcol[i];
            if (p[j] == 0) p[j] = i;       // tight edge: c - u - 0 == 0
            else           freelist[numfree++] = i;
        }
    }
    numfree = __shfl_sync(FULL, numfree, 0);
    __syncwarp();

    // per-lane duals for owned columns (v = 0 everywhere initially)
    double v[16];
    float  vf[16];
#pragma unroll
    for (int c = 0; c < 16; c++) { v[c] = 0.0; vf[c] = 0.0f; }

    // ---- Phase C: exact Dijkstra augmentation (R3-proven machinery) ------
    for (int t = 0; t < numfree; t++) {
        int i = freelist[t];

        unsigned long long msort[16];   // exact sorted-bits of minv (shifted)
        float minvf[16];                // fp32 approx (filter key)
#pragma unroll
        for (int c = 0; c < 16; c++) { msort[c] = MAXU64; minvf[c] = 3.0e38f; }
        unsigned long long lmin = MAXU64;
        int lidx = 0;
        unsigned umask = 0;
        double D = 0.0;
        int i0 = i;
        int j0 = 0;
        if (lane == 0) p[0] = i;
        __syncwarp();

        int jsel;
        double Df;

        while (true) {
            double h = D - u[i0];
            float hf = (float)h;
            const float* crow = cbase + (size_t)(i0 - 1) * NN;

            float f[16];
#pragma unroll
            for (int c = 0; c < 16; c++) f[c] = __ldg(crow + c * 32 + lane);

            // fp32 filter: which columns might improve?
            unsigned pmask = 0;
#pragma unroll
            for (int c = 0; c < 16; c++) {
                float curf = (f[c] - vf[c]) + hf;
                if (curf < minvf[c] + GUARD) pmask |= 1u << c;
            }

            // exact fp64 updates only for filtered columns
            while (pmask) {
                int c = __ffs(pmask) - 1;
                pmask &= pmask - 1;
                double cur = ((double)f[c] + h) - v[c];
                unsigned long long cs = dsort(cur);
                if (cs < msort[c]) {
                    msort[c] = cs;
                    minvf[c] = (float)cur;
                    way[c * 32 + lane + 1] = j0;
                    if (cs < lmin) { lmin = cs; lidx = c; }
                }
            }

            // warp argmin: exact value via 2x REDUX on sorted bits, index
            // (= j-1, exact lowest-j tie-break) via 3rd REDUX on 32*c+lane.
            unsigned hi = (unsigned)(lmin >> 32);
            unsigned mh = __reduce_min_sync(FULL, hi);
            unsigned lo = (hi == mh) ? (unsigned)lmin : 0xFFFFFFFFu;
            unsigned ml = __reduce_min_sync(FULL, lo);
            bool win = (hi == mh) && ((unsigned)lmin == ml);
            unsigned key = win ? (unsigned)(lidx * 32 + lane) : 0xFFFFFFFFu;
            unsigned mk = __reduce_min_sync(FULL, key);
            int j1 = (int)mk + 1;

            unsigned long long wsv = __shfl_sync(FULL, lmin, (int)(mk & 31u));
            double Dnew = dunsort(wsv);
            D = Dnew;

            int pj1 = p[j1];           // broadcast LDS, warp-uniform
            if (pj1 == 0) { jsel = j1; Df = Dnew; break; }

            // mark j1 used (winner lane only) + rebuild its local min
            if (lane == (int)(mk & 31u)) {
                int mc = (int)(mk >> 5);
                umask |= 1u << mc;
                msort[mc] = MAXU64;
                minvf[mc] = -3.0e38f;   // filter can never pass again
                sarr[j1 - 1] = Dnew;
                lmin = MAXU64; lidx = 0;
#pragma unroll
                for (int c2 = 0; c2 < 16; c2++)
                    if (msort[c2] < lmin) { lmin = msort[c2]; lidx = c2; }
            }
            i0 = pj1;
            j0 = j1;
        }

        // deferred dual updates (p[] is pre-augmentation; only USED = matched
        // columns get v updates, so free columns keep v = 0 forever)
        unsigned um = umask;
        while (um) {
            int c = __ffs(um) - 1; um &= um - 1;
            int j = c * 32 + lane + 1;
            double adj = Df - sarr[j - 1];
            v[c] -= adj;
            vf[c] = (float)v[c];
            int r = p[j];              // distinct rows across used columns
            u[r] += adj;
        }
        if (lane == 0) u[i] += Df;
        __syncwarp();

        if (lane == 0) {
            int j0a = jsel;
            while (j0a) { int jp = way[j0a]; p[j0a] = p[jp]; j0a = jp; }
        }
        __syncwarp();
    }

    // perm: matched original rows ascending, then unmatched ascending
    int mbase = b * NN, mo = 0, uo = MM;
#pragma unroll
    for (int c = 0; c < 16; c++) {
        int j = c * 32 + lane + 1;
        bool mt = (p[j] != 0);
        unsigned bal = __ballot_sync(FULL, mt);
        unsigned ltm = (lane == 0) ? 0u : (FULL >> (32 - lane));
        int lt  = __popc(bal & ltm);
        int ltu = __popc((~bal) & ltm);
        if (mt)  g_perm[mbase + mo + lt]  = j - 1;
        if (!mt) g_perm[mbase + uo + ltu] = j - 1;
        mo += __popc(bal);
        uo += 32 - __popc(bal);
    }
}

// ---------------------------------------------------------------------------
// Gather: out[b][k] = seq1[b][perm[b][k]]
// ---------------------------------------------------------------------------
__global__ void gather_kernel(const float* __restrict__ seq1,
                              float* __restrict__ out) {
    int b   = blockIdx.y;
    int row = blockIdx.x;
    int src = g_perm[b * NN + row];
    const float4* s = (const float4*)(seq1 + ((size_t)b * NN + src) * DD);
    float4*       d = (float4*)(out  + ((size_t)b * NN + row) * DD);
    int k = threadIdx.x;
    d[k] = s[k];
}

// ---------------------------------------------------------------------------
extern "C" void kernel_launch(void* const* d_in, const int* in_sizes, int n_in,
                              void* d_out, int out_size) {
    const float* seq1 = (const float*)d_in[0];
    const float* seq2 = (const float*)d_in[1];
    float* out = (float*)d_out;

    int totalRows = BB * (NN + MM);
    norms_kernel<<<totalRows / 8, 256>>>(seq1, seq2);

    dim3 gc(NN / TBN, MM / TBM, BB);
    cost_kernel<<<gc, 256>>>(seq1, seq2);

    jv_warp_kernel<<<BB, 32>>>();

    gather_kernel<<<dim3(NN, BB), DD / 4>>>(seq1, out);
}

// round 9
// speedup vs baseline: 2.1251x; 1.1695x over previous
#include <cuda_runtime.h>

#define BB 16
#define NN 512   // seq1 rows (columns of transposed cost)
#define MM 448   // seq2 rows (rows of transposed cost)
#define DD 1536
#define FULL 0xffffffffu

// cost_t[b][m][n] = ||seq1[b][n] - seq2[b][m]||  (transposed layout for JV)
__device__ float g_cost[BB * MM * NN];
__device__ float g_n1[BB * NN];
__device__ float g_n2[BB * MM];
__device__ int   g_perm[BB * NN];

// ---------------------------------------------------------------------------
// Row norms: one warp per row.
// ---------------------------------------------------------------------------
__global__ void norms_kernel(const float* __restrict__ seq1,
                             const float* __restrict__ seq2) {
    int warp = (blockIdx.x * blockDim.x + threadIdx.x) >> 5;
    int lane = threadIdx.x & 31;
    int total = BB * (NN + MM);
    if (warp >= total) return;
    const float* ptr;
    float* out;
    if (warp < BB * NN) {
        ptr = seq1 + (size_t)warp * DD;
        out = g_n1 + warp;
    } else {
        int w = warp - BB * NN;
        ptr = seq2 + (size_t)w * DD;
        out = g_n2 + w;
    }
    float s = 0.f;
    for (int k = lane * 4; k < DD; k += 32 * 4) {
        float4 v = *(const float4*)(ptr + k);
        s += v.x * v.x + v.y * v.y + v.z * v.z + v.w * v.w;
    }
#pragma unroll
    for (int o = 16; o > 0; o >>= 1) s += __shfl_down_sync(FULL, s, o);
    if (lane == 0) *out = s;
}

// ---------------------------------------------------------------------------
// Cost matrix: tiled fp32 GEMM  dot = seq2[m] . seq1[n], then sqrt epilogue.
// ---------------------------------------------------------------------------
#define TBM 64
#define TBN 64
#define TBK 16

__global__ void __launch_bounds__(256) cost_kernel(const float* __restrict__ seq1,
                                                   const float* __restrict__ seq2) {
    __shared__ float As[TBK][TBM + 4];
    __shared__ float Bs[TBK][TBN + 4];

    int b  = blockIdx.z;
    int m0 = blockIdx.y * TBM;
    int n0 = blockIdx.x * TBN;
    const float* A  = seq2 + ((size_t)b * MM + m0) * DD;
    const float* Bp = seq1 + ((size_t)b * NN + n0) * DD;

    int tid = threadIdx.x;
    int lr  = tid >> 2;
    int lc  = (tid & 3) * 4;
    int ty  = tid >> 4;
    int tx  = tid & 15;

    float acc[4][4] = {};

    for (int k0 = 0; k0 < DD; k0 += TBK) {
        float4 av = *(const float4*)(A  + (size_t)lr * DD + k0 + lc);
        float4 bv = *(const float4*)(Bp + (size_t)lr * DD + k0 + lc);
        __syncthreads();
        As[lc + 0][lr] = av.x; As[lc + 1][lr] = av.y;
        As[lc + 2][lr] = av.z; As[lc + 3][lr] = av.w;
        Bs[lc + 0][lr] = bv.x; Bs[lc + 1][lr] = bv.y;
        Bs[lc + 2][lr] = bv.z; Bs[lc + 3][lr] = bv.w;
        __syncthreads();
#pragma unroll
        for (int k = 0; k < TBK; k++) {
            float4 a  = *(const float4*)&As[k][ty * 4];
            float4 bb = *(const float4*)&Bs[k][tx * 4];
            float ar[4] = {a.x, a.y, a.z, a.w};
            float br[4] = {bb.x, bb.y, bb.z, bb.w};
#pragma unroll
            for (int im = 0; im < 4; im++)
#pragma unroll
                for (int in = 0; in < 4; in++)
                    acc[im][in] += ar[im] * br[in];
        }
    }

#pragma unroll
    for (int im = 0; im < 4; im++) {
        int m = m0 + ty * 4 + im;
        float nm = g_n2[b * MM + m];
#pragma unroll
        for (int in = 0; in < 4; in++) {
            int n = n0 + tx * 4 + in;
            float d2 = nm + g_n1[b * NN + n] - 2.0f * acc[im][in];
            g_cost[((size_t)b * MM + m) * NN + n] = sqrtf(fmaxf(d2, 0.0f));
        }
    }
}

// ---------------------------------------------------------------------------
// LAPJV (rectangular-safe): row reduction + greedy tight seeding +
// augmenting row reduction (v=0 base; v only changes on columns at the
// moment they get matched, and matched columns never unmatch -> free
// columns keep v = 0 forever, the rectangular-duality invariant) +
// exact Dijkstra augmentation.
// One warp per batch; lane owns columns j-1 = 32*c + lane, c = 0..15.
// ---------------------------------------------------------------------------
#define MAXU64 0xFFFFFFFFFFFFFFFFULL
#define GUARD  1e-3f

__device__ __forceinline__ unsigned long long dsort(double d) {
    long long x = __double_as_longlong(d);
    return (unsigned long long)(x ^ ((x >> 63) | 0x8000000000000000LL));
}
__device__ __forceinline__ double dunsort(unsigned long long u) {
    long long x = (long long)u;
    long long b = (x < 0) ? (x ^ 0x8000000000000000LL) : ~x;
    return __longlong_as_double(b);
}

__global__ void __launch_bounds__(32) jv_warp_kernel() {
    __shared__ double u[MM + 1];     // row potentials
    __shared__ double vsh[NN + 1];   // column potentials (phases A-B2)
    __shared__ double sarr[NN];      // D at marking time, per column
    __shared__ int    p[NN + 1];     // column -> assigned row (1-based), 0=free
    __shared__ int    way[NN + 1];
    __shared__ int    argcol[MM + 1];// row -> argmin column (1-based)
    __shared__ int    freelist[MM];

    int b = blockIdx.x;
    const float* cbase = g_cost + (size_t)b * MM * NN;
    int lane = threadIdx.x;

    for (int t = lane; t < NN + 1; t += 32) { p[t] = 0; way[t] = 0; vsh[t] = 0.0; }
    __syncwarp();

    // ---- Phase A: row reduction  u[i] = min_j c[i][j], record argmin -----
    for (int i = 1; i <= MM; i++) {
        const float* crow = cbase + (size_t)(i - 1) * NN;
        float m = 3.0e38f;
        int bj = 0x7fffffff;
#pragma unroll
        for (int c = 0; c < 16; c++) {
            float f = __ldg(crow + c * 32 + lane);
            if (f < m) { m = f; bj = c * 32 + lane; }
        }
#pragma unroll
        for (int o = 16; o > 0; o >>= 1) {
            float om = __shfl_xor_sync(FULL, m, o);
            int obj = __shfl_xor_sync(FULL, bj, o);
            if (om < m || (om == m && obj < bj)) { m = om; bj = obj; }
        }
        if (lane == 0) { u[i] = (double)m; argcol[i] = bj + 1; }
    }
    __syncwarp();

    // ---- Phase B: greedy tight seeding (lane 0, serial) ------------------
    int numfree = 0;
    if (lane == 0) {
        for (int i = 1; i <= MM; i++) {
            int j = argcol[i];
            if (p[j] == 0) p[j] = i;       // tight: c - u - 0 == 0
            else           freelist[numfree++] = i;
        }
    }
    numfree = __shfl_sync(FULL, numfree, 0);
    __syncwarp();

    // ---- Phase B2: augmenting row reduction (2 bounded sweeps) -----------
    // From v=0 base. v[j1] is lowered ONLY at the moment j1 becomes matched
    // to fr (and matched columns never unmatch), so free columns keep v=0.
    for (int sweep = 0; sweep < 2; sweep++) {
        int prv = numfree;
        int nf2 = 0;
        for (int k = 0; k < prv; k++) {
            int fr = freelist[k];
            const float* crow = cbase + (size_t)(fr - 1) * NN;
            unsigned long long m1 = MAXU64, m2 = MAXU64;
            int bj = 0x7fffffff;
#pragma unroll
            for (int c = 0; c < 16; c++) {
                float f = __ldg(crow + c * 32 + lane);
                double cur = (double)f - vsh[c * 32 + lane + 1];
                unsigned long long cs = dsort(cur);
                if (cs < m1) { m2 = m1; m1 = cs; bj = c * 32 + lane; }
                else if (cs < m2) m2 = cs;
            }
            // warp merge of (min1, argmin1, min2); index tie-break keeps
            // ALL lanes converged on the same bj even on exact fp64 ties.
#pragma unroll
            for (int o = 16; o > 0; o >>= 1) {
                unsigned long long om1 = __shfl_xor_sync(FULL, m1, o);
                unsigned long long om2 = __shfl_xor_sync(FULL, m2, o);
                int obj = __shfl_xor_sync(FULL, bj, o);
                bool take = (om1 < m1) || (om1 == m1 && obj < bj);
                unsigned long long ca = take ? om2 : m2;
                unsigned long long cb = take ? m1  : om1;
                if (take) { m1 = om1; bj = obj; }
                m2 = (cb < ca) ? cb : ca;
            }
            int j1 = bj + 1;                 // warp-uniform
            double u1 = dunsort(m1);
            double u2 = dunsort(m2);

            int i1 = p[j1];                  // ALL lanes read first...
            __syncwarp();                    // ...ordered before writes
            if (lane == 0) {
                u[fr] = u2;                  // tight (+feasible: others >= m2)
                if (m1 < m2) vsh[j1] -= (u2 - u1);
                p[j1] = fr;
            }
            __syncwarp();
            if (i1) {                        // uniform across warp
                if (lane == 0) freelist[nf2] = i1;   // nf2 <= k: in-place safe
                nf2++;
                __syncwarp();
            }
        }
        numfree = nf2;
    }
    __syncwarp();

    // per-lane duals for owned columns (from B2 result)
    double v[16];
    float  vf[16];
#pragma unroll
    for (int c = 0; c < 16; c++) {
        v[c]  = vsh[c * 32 + lane + 1];
        vf[c] = (float)v[c];
    }

    // ---- Phase C: exact Dijkstra augmentation (R3/R8-proven machinery) ---
    for (int t = 0; t < numfree; t++) {
        int i = freelist[t];

        unsigned long long msort[16];   // exact sorted-bits of minv (shifted)
        float minvf[16];                // fp32 approx of minv
        float thr[16];                  // filter threshold = minvf + vf + GUARD
#pragma unroll
        for (int c = 0; c < 16; c++) {
            msort[c] = MAXU64; minvf[c] = 3.0e38f; thr[c] = 3.0e38f;
        }
        unsigned long long lmin = MAXU64;
        int lidx = 0;
        unsigned umask = 0;
        double D = 0.0;
        int i0 = i;
        int j0 = 0;
        if (lane == 0) p[0] = i;
        __syncwarp();

        int jsel;
        double Df;

        while (true) {
            double h = D - u[i0];
            float hf = (float)h;
            const float* crow = cbase + (size_t)(i0 - 1) * NN;

            float f[16];
#pragma unroll
            for (int c = 0; c < 16; c++) f[c] = __ldg(crow + c * 32 + lane);

            // fp32 filter: 1 FADD + 1 FSETP per column
            unsigned pmask = 0;
#pragma unroll
            for (int c = 0; c < 16; c++)
                if (f[c] + hf < thr[c]) pmask |= 1u << c;

            // exact fp64 updates only for filtered columns
            while (pmask) {
                int c = __ffs(pmask) - 1;
                pmask &= pmask - 1;
                double cur = ((double)f[c] + h) - v[c];
                unsigned long long cs = dsort(cur);
                if (cs < msort[c]) {
                    msort[c] = cs;
                    minvf[c] = (float)cur;
                    thr[c]   = minvf[c] + vf[c] + GUARD;
                    way[c * 32 + lane + 1] = j0;
                    if (cs < lmin) { lmin = cs; lidx = c; }
                }
            }

            // warp argmin: exact value via 2x REDUX on sorted bits; winner
            // lane via ballot (any consistent warp-uniform tie-break is OK;
            // the optimum is unique for generic data).
            unsigned hi = (unsigned)(lmin >> 32);
            unsigned mh = __reduce_min_sync(FULL, hi);
            unsigned lo = (hi == mh) ? (unsigned)lmin : 0xFFFFFFFFu;
            unsigned ml = __reduce_min_sync(FULL, lo);
            bool win = (hi == mh) && ((unsigned)lmin == ml);
            unsigned bal = __ballot_sync(FULL, win);
            int wl = __ffs(bal) - 1;                       // winner lane
            int widx = __shfl_sync(FULL, lidx, wl);
            unsigned long long wsv = __shfl_sync(FULL, lmin, wl);
            int j1 = widx * 32 + wl + 1;

            double Dnew = dunsort(wsv);
            D = Dnew;

            int pj1 = p[j1];           // broadcast LDS, warp-uniform
            if (pj1 == 0) { jsel = j1; Df = Dnew; break; }

            // mark j1 used (winner lane only) + rebuild its local min
            if (lane == wl) {
                umask |= 1u << widx;
                msort[widx] = MAXU64;
                minvf[widx] = -3.0e38f;
                thr[widx]   = -3.0e38f;    // filter can never pass again
                sarr[j1 - 1] = Dnew;
                lmin = MAXU64; lidx = 0;
#pragma unroll
                for (int c2 = 0; c2 < 16; c2++)
                    if (msort[c2] < lmin) { lmin = msort[c2]; lidx = c2; }
            }
            i0 = pj1;
            j0 = j1;
        }

        // deferred dual updates (p[] is pre-augmentation; only USED = matched
        // columns get v updates, so free columns keep v = 0 forever)
        unsigned um = umask;
        while (um) {
            int c = __ffs(um) - 1; um &= um - 1;
            int j = c * 32 + lane + 1;
            double adj = Df - sarr[j - 1];
            v[c] -= adj;
            vf[c] = (float)v[c];
            int r = p[j];              // distinct rows across used columns
            u[r] += adj;
        }
        if (lane == 0) u[i] += Df;
        __syncwarp();

        if (lane == 0) {
            int j0a = jsel;
            while (j0a) { int jp = way[j0a]; p[j0a] = p[jp]; j0a = jp; }
        }
        __syncwarp();
    }

    // perm: matched original rows ascending, then unmatched ascending
    int mbase = b * NN, mo = 0, uo = MM;
#pragma unroll
    for (int c = 0; c < 16; c++) {
        int j = c * 32 + lane + 1;
        bool mt = (p[j] != 0);
        unsigned bal = __ballot_sync(FULL, mt);
        unsigned ltm = (lane == 0) ? 0u : (FULL >> (32 - lane));
        int lt  = __popc(bal & ltm);
        int ltu = __popc((~bal) & ltm);
        if (mt)  g_perm[mbase + mo + lt]  = j - 1;
        if (!mt) g_perm[mbase + uo + ltu] = j - 1;
        mo += __popc(bal);
        uo += 32 - __popc(bal);
    }
}

// ---------------------------------------------------------------------------
// Gather: out[b][k] = seq1[b][perm[b][k]]
// ---------------------------------------------------------------------------
__global__ void gather_kernel(const float* __restrict__ seq1,
                              float* __restrict__ out) {
    int b   = blockIdx.y;
    int row = blockIdx.x;
    int src = g_perm[b * NN + row];
    const float4* s = (const float4*)(seq1 + ((size_t)b * NN + src) * DD);
    float4*       d = (float4*)(out  + ((size_t)b * NN + row) * DD);
    int k = threadIdx.x;
    d[k] = s[k];
}

// ---------------------------------------------------------------------------
extern "C" void kernel_launch(void* const* d_in, const int* in_sizes, int n_in,
                              void* d_out, int out_size) {
    const float* seq1 = (const float*)d_in[0];
    const float* seq2 = (const float*)d_in[1];
    float* out = (float*)d_out;

    int totalRows = BB * (NN + MM);
    norms_kernel<<<totalRows / 8, 256>>>(seq1, seq2);

    dim3 gc(NN / TBN, MM / TBM, BB);
    cost_kernel<<<gc, 256>>>(seq1, seq2);

    jv_warp_kernel<<<BB, 32>>>();

    gather_kernel<<<dim3(NN, BB), DD / 4>>>(seq1, out);
}

// round 10
// speedup vs baseline: 3.8632x; 1.8179x over previous
#include <cuda_runtime.h>

#define BB 16
#define NN 512   // seq1 rows (columns of transposed cost)
#define MM 448   // seq2 rows (rows of transposed cost)
#define DD 1536
#define FULL 0xffffffffu

// cost_t[b][m][n] = ||seq1[b][n] - seq2[b][m]||  (transposed layout for JV)
__device__ float g_cost[BB * MM * NN];
__device__ float g_n1[BB * NN];
__device__ float g_n2[BB * MM];
__device__ int   g_perm[BB * NN];

// ---------------------------------------------------------------------------
// Row norms: one warp per row.
// ---------------------------------------------------------------------------
__global__ void norms_kernel(const float* __restrict__ seq1,
                             const float* __restrict__ seq2) {
    int warp = (blockIdx.x * blockDim.x + threadIdx.x) >> 5;
    int lane = threadIdx.x & 31;
    int total = BB * (NN + MM);
    if (warp >= total) return;
    const float* ptr;
    float* out;
    if (warp < BB * NN) {
        ptr = seq1 + (size_t)warp * DD;
        out = g_n1 + warp;
    } else {
        int w = warp - BB * NN;
        ptr = seq2 + (size_t)w * DD;
        out = g_n2 + w;
    }
    float s = 0.f;
    for (int k = lane * 4; k < DD; k += 32 * 4) {
        float4 v = *(const float4*)(ptr + k);
        s += v.x * v.x + v.y * v.y + v.z * v.z + v.w * v.w;
    }
#pragma unroll
    for (int o = 16; o > 0; o >>= 1) s += __shfl_down_sync(FULL, s, o);
    if (lane == 0) *out = s;
}

// ---------------------------------------------------------------------------
// Cost matrix: tiled fp32 GEMM  dot = seq2[m] . seq1[n], then sqrt epilogue.
// ---------------------------------------------------------------------------
#define TBM 64
#define TBN 64
#define TBK 16

__global__ void __launch_bounds__(256) cost_kernel(const float* __restrict__ seq1,
                                                   const float* __restrict__ seq2) {
    __shared__ float As[TBK][TBM + 4];
    __shared__ float Bs[TBK][TBN + 4];

    int b  = blockIdx.z;
    int m0 = blockIdx.y * TBM;
    int n0 = blockIdx.x * TBN;
    const float* A  = seq2 + ((size_t)b * MM + m0) * DD;
    const float* Bp = seq1 + ((size_t)b * NN + n0) * DD;

    int tid = threadIdx.x;
    int lr  = tid >> 2;
    int lc  = (tid & 3) * 4;
    int ty  = tid >> 4;
    int tx  = tid & 15;

    float acc[4][4] = {};

    for (int k0 = 0; k0 < DD; k0 += TBK) {
        float4 av = *(const float4*)(A  + (size_t)lr * DD + k0 + lc);
        float4 bv = *(const float4*)(Bp + (size_t)lr * DD + k0 + lc);
        __syncthreads();
        As[lc + 0][lr] = av.x; As[lc + 1][lr] = av.y;
        As[lc + 2][lr] = av.z; As[lc + 3][lr] = av.w;
        Bs[lc + 0][lr] = bv.x; Bs[lc + 1][lr] = bv.y;
        Bs[lc + 2][lr] = bv.z; Bs[lc + 3][lr] = bv.w;
        __syncthreads();
#pragma unroll
        for (int k = 0; k < TBK; k++) {
            float4 a  = *(const float4*)&As[k][ty * 4];
            float4 bb = *(const float4*)&Bs[k][tx * 4];
            float ar[4] = {a.x, a.y, a.z, a.w};
            float br[4] = {bb.x, bb.y, bb.z, bb.w};
#pragma unroll
            for (int im = 0; im < 4; im++)
#pragma unroll
                for (int in = 0; in < 4; in++)
                    acc[im][in] += ar[im] * br[in];
        }
    }

#pragma unroll
    for (int im = 0; im < 4; im++) {
        int m = m0 + ty * 4 + im;
        float nm = g_n2[b * MM + m];
#pragma unroll
        for (int in = 0; in < 4; in++) {
            int n = n0 + tx * 4 + in;
            float d2 = nm + g_n1[b * NN + n] - 2.0f * acc[im][in];
            g_cost[((size_t)b * MM + m) * NN + n] = sqrtf(fmaxf(d2, 0.0f));
        }
    }
}

// ---------------------------------------------------------------------------
// LAPJV (rectangular-safe): row reduction + greedy tight seeding +
// iterated augmenting row reduction (auction sweeps, v=0 base; v changes
// only on columns at the moment they get matched; matched columns never
// unmatch -> free columns keep v = 0, the rectangular-duality invariant) +
// exact Dijkstra augmentation for the remainder.
// One warp per batch; lane owns columns j-1 = 32*c + lane, c = 0..15.
// ---------------------------------------------------------------------------
#define MAXU64 0xFFFFFFFFFFFFFFFFULL
#define GUARD  1e-4f
#define ARR_SWEEPS 16

__device__ __forceinline__ unsigned long long dsort(double d) {
    long long x = __double_as_longlong(d);
    return (unsigned long long)(x ^ ((x >> 63) | 0x8000000000000000LL));
}
__device__ __forceinline__ double dunsort(unsigned long long u) {
    long long x = (long long)u;
    long long b = (x < 0) ? (x ^ 0x8000000000000000LL) : ~x;
    return __longlong_as_double(b);
}

__global__ void __launch_bounds__(32) jv_warp_kernel() {
    __shared__ double u[MM + 1];     // row potentials
    __shared__ double vsh[NN + 1];   // column potentials (phases A-B2)
    __shared__ double sarr[NN];      // D at marking time, per column
    __shared__ int    p[NN + 1];     // column -> assigned row (1-based), 0=free
    __shared__ int    way[NN + 1];
    __shared__ int    argcol[MM + 1];// row -> argmin column (1-based)
    __shared__ int    freelist[MM];

    int b = blockIdx.x;
    const float* cbase = g_cost + (size_t)b * MM * NN;
    int lane = threadIdx.x;

    for (int t = lane; t < NN + 1; t += 32) { p[t] = 0; way[t] = 0; vsh[t] = 0.0; }
    __syncwarp();

    // ---- Phase A: row reduction  u[i] = min_j c[i][j], record argmin -----
    for (int i = 1; i <= MM; i++) {
        const float* crow = cbase + (size_t)(i - 1) * NN;
        float m = 3.0e38f;
        int bj = 0x7fffffff;
#pragma unroll
        for (int c = 0; c < 16; c++) {
            float f = __ldg(crow + c * 32 + lane);
            if (f < m) { m = f; bj = c * 32 + lane; }
        }
#pragma unroll
        for (int o = 16; o > 0; o >>= 1) {
            float om = __shfl_xor_sync(FULL, m, o);
            int obj = __shfl_xor_sync(FULL, bj, o);
            if (om < m || (om == m && obj < bj)) { m = om; bj = obj; }
        }
        if (lane == 0) { u[i] = (double)m; argcol[i] = bj + 1; }
    }
    __syncwarp();

    // ---- Phase B: greedy tight seeding (lane 0, serial) ------------------
    int numfree = 0;
    if (lane == 0) {
        for (int i = 1; i <= MM; i++) {
            int j = argcol[i];
            if (p[j] == 0) p[j] = i;       // tight: c - u - 0 == 0
            else           freelist[numfree++] = i;
        }
    }
    numfree = __shfl_sync(FULL, numfree, 0);
    __syncwarp();

    // ---- Phase B2: iterated augmenting row reduction (auction sweeps) ----
    // Gauss-Seidel auction with eps=0: each displacement strictly lowers the
    // contested column's v, diverting rows toward free columns over sweeps.
    // One sweep ~60us; each row it assigns saves a ~150us Dijkstra.
    for (int sweep = 0; sweep < ARR_SWEEPS && numfree > 0; sweep++) {
        int prv = numfree;
        int nf2 = 0;
        for (int k = 0; k < prv; k++) {
            int fr = freelist[k];
            const float* crow = cbase + (size_t)(fr - 1) * NN;
            unsigned long long m1 = MAXU64, m2 = MAXU64;
            int bj = 0x7fffffff;
#pragma unroll
            for (int c = 0; c < 16; c++) {
                float f = __ldg(crow + c * 32 + lane);
                double cur = (double)f - vsh[c * 32 + lane + 1];
                unsigned long long cs = dsort(cur);
                if (cs < m1) { m2 = m1; m1 = cs; bj = c * 32 + lane; }
                else if (cs < m2) m2 = cs;
            }
            // warp merge of (min1, argmin1, min2); index tie-break keeps
            // ALL lanes converged on the same bj even on exact fp64 ties.
#pragma unroll
            for (int o = 16; o > 0; o >>= 1) {
                unsigned long long om1 = __shfl_xor_sync(FULL, m1, o);
                unsigned long long om2 = __shfl_xor_sync(FULL, m2, o);
                int obj = __shfl_xor_sync(FULL, bj, o);
                bool take = (om1 < m1) || (om1 == m1 && obj < bj);
                unsigned long long ca = take ? om2 : m2;
                unsigned long long cb = take ? m1  : om1;
                if (take) { m1 = om1; bj = obj; }
                m2 = (cb < ca) ? cb : ca;
            }
            int j1 = bj + 1;                 // warp-uniform
            double u1 = dunsort(m1);
            double u2 = dunsort(m2);

            int i1 = p[j1];                  // ALL lanes read first...
            __syncwarp();                    // ...ordered before writes
            if (lane == 0) {
                u[fr] = u2;                  // tight (+feasible: others >= m2)
                if (m1 < m2) vsh[j1] -= (u2 - u1);
                p[j1] = fr;
            }
            __syncwarp();
            if (i1) {                        // uniform across warp
                if (lane == 0) freelist[nf2] = i1;   // nf2 <= k: in-place safe
                nf2++;
                __syncwarp();
            }
        }
        numfree = nf2;
    }
    __syncwarp();

    // per-lane duals for owned columns (from B2 result)
    double v[16];
    float  vf[16];
#pragma unroll
    for (int c = 0; c < 16; c++) {
        v[c]  = vsh[c * 32 + lane + 1];
        vf[c] = (float)v[c];
    }

    // ---- Phase C: exact Dijkstra augmentation (R3/R8-proven machinery) ---
    for (int t = 0; t < numfree; t++) {
        int i = freelist[t];

        unsigned long long msort[16];   // exact sorted-bits of minv (shifted)
        float minvf[16];                // fp32 approx of minv
        float thr[16];                  // filter threshold = minvf + vf + GUARD
#pragma unroll
        for (int c = 0; c < 16; c++) {
            msort[c] = MAXU64; minvf[c] = 3.0e38f; thr[c] = 3.0e38f;
        }
        unsigned long long lmin = MAXU64;
        int lidx = 0;
        unsigned umask = 0;
        double D = 0.0;
        int i0 = i;
        int j0 = 0;
        if (lane == 0) p[0] = i;
        __syncwarp();

        int jsel;
        double Df;

        while (true) {
            double h = D - u[i0];
            float hf = (float)h;
            const float* crow = cbase + (size_t)(i0 - 1) * NN;

            float f[16];
#pragma unroll
            for (int c = 0; c < 16; c++) f[c] = __ldg(crow + c * 32 + lane);

            // fp32 filter: 1 FADD + 1 FSETP per column
            unsigned pmask = 0;
#pragma unroll
            for (int c = 0; c < 16; c++)
                if (f[c] + hf < thr[c]) pmask |= 1u << c;

            // exact fp64 updates only for filtered columns
            while (pmask) {
                int c = __ffs(pmask) - 1;
                pmask &= pmask - 1;
                double cur = ((double)f[c] + h) - v[c];
                unsigned long long cs = dsort(cur);
                if (cs < msort[c]) {
                    msort[c] = cs;
                    minvf[c] = (float)cur;
                    thr[c]   = minvf[c] + vf[c] + GUARD;
                    way[c * 32 + lane + 1] = j0;
                    if (cs < lmin) { lmin = cs; lidx = c; }
                }
            }

            // warp argmin: exact value via 2x REDUX on sorted bits; winner
            // lane via ballot (consistent warp-uniform tie-break).
            unsigned hi = (unsigned)(lmin >> 32);
            unsigned mh = __reduce_min_sync(FULL, hi);
            unsigned lo = (hi == mh) ? (unsigned)lmin : 0xFFFFFFFFu;
            unsigned ml = __reduce_min_sync(FULL, lo);
            bool win = (hi == mh) && ((unsigned)lmin == ml);
            unsigned bal = __ballot_sync(FULL, win);
            int wl = __ffs(bal) - 1;                       // winner lane
            int widx = __shfl_sync(FULL, lidx, wl);
            unsigned long long wsv = __shfl_sync(FULL, lmin, wl);
            int j1 = widx * 32 + wl + 1;

            double Dnew = dunsort(wsv);
            D = Dnew;

            int pj1 = p[j1];           // broadcast LDS, warp-uniform
            if (pj1 == 0) { jsel = j1; Df = Dnew; break; }

            // mark j1 used (winner lane only) + rebuild its local min
            if (lane == wl) {
                umask |= 1u << widx;
                msort[widx] = MAXU64;
                minvf[widx] = -3.0e38f;
                thr[widx]   = -3.0e38f;    // filter can never pass again
                sarr[j1 - 1] = Dnew;
                lmin = MAXU64; lidx = 0;
#pragma unroll
                for (int c2 = 0; c2 < 16; c2++)
                    if (msort[c2] < lmin) { lmin = msort[c2]; lidx = c2; }
            }
            i0 = pj1;
            j0 = j1;
        }

        // deferred dual updates (p[] is pre-augmentation; only USED = matched
        // columns get v updates, so free columns keep v = 0 forever)
        unsigned um = umask;
        while (um) {
            int c = __ffs(um) - 1; um &= um - 1;
            int j = c * 32 + lane + 1;
            double adj = Df - sarr[j - 1];
            v[c] -= adj;
            vf[c] = (float)v[c];
            int r = p[j];              // distinct rows across used columns
            u[r] += adj;
        }
        if (lane == 0) u[i] += Df;
        __syncwarp();

        if (lane == 0) {
            int j0a = jsel;
            while (j0a) { int jp = way[j0a]; p[j0a] = p[jp]; j0a = jp; }
        }
        __syncwarp();
    }

    // perm: matched original rows ascending, then unmatched ascending
    int mbase = b * NN, mo = 0, uo = MM;
#pragma unroll
    for (int c = 0; c < 16; c++) {
        int j = c * 32 + lane + 1;
        bool mt = (p[j] != 0);
        unsigned bal = __ballot_sync(FULL, mt);
        unsigned ltm = (lane == 0) ? 0u : (FULL >> (32 - lane));
        int lt  = __popc(bal & ltm);
        int ltu = __popc((~bal) & ltm);
        if (mt)  g_perm[mbase + mo + lt]  = j - 1;
        if (!mt) g_perm[mbase + uo + ltu] = j - 1;
        mo += __popc(bal);
        uo += 32 - __popc(bal);
    }
}

// ---------------------------------------------------------------------------
// Gather: out[b][k] = seq1[b][perm[b][k]]
// ---------------------------------------------------------------------------
__global__ void gather_kernel(const float* __restrict__ seq1,
                              float* __restrict__ out) {
    int b   = blockIdx.y;
    int row = blockIdx.x;
    int src = g_perm[b * NN + row];
    const float4* s = (const float4*)(seq1 + ((size_t)b * NN + src) * DD);
    float4*       d = (float4*)(out  + ((size_t)b * NN + row) * DD);
    int k = threadIdx.x;
    d[k] = s[k];
}

// ---------------------------------------------------------------------------
extern "C" void kernel_launch(void* const* d_in, const int* in_sizes, int n_in,
                              void* d_out, int out_size) {
    const float* seq1 = (const float*)d_in[0];
    const float* seq2 = (const float*)d_in[1];
    float* out = (float*)d_out;

    int totalRows = BB * (NN + MM);
    norms_kernel<<<totalRows / 8, 256>>>(seq1, seq2);

    dim3 gc(NN / TBN, MM / TBM, BB);
    cost_kernel<<<gc, 256>>>(seq1, seq2);

    jv_warp_kernel<<<BB, 32>>>();

    gather_kernel<<<dim3(NN, BB), DD / 4>>>(seq1, out);
}

// round 11
// speedup vs baseline: 4.3192x; 1.1180x over previous
#include <cuda_runtime.h>

#define BB 16
#define NN 512   // seq1 rows (columns of transposed cost)
#define MM 448   // seq2 rows (rows of transposed cost)
#define DD 1536
#define FULL 0xffffffffu

// cost_t[b][m][n] = ||seq1[b][n] - seq2[b][m]||  (transposed layout for JV)
__device__ float g_cost[BB * MM * NN];
__device__ float g_n1[BB * NN];
__device__ float g_n2[BB * MM];
__device__ int   g_perm[BB * NN];

// ---------------------------------------------------------------------------
// Row norms: one warp per row.
// ---------------------------------------------------------------------------
__global__ void norms_kernel(const float* __restrict__ seq1,
                             const float* __restrict__ seq2) {
    int warp = (blockIdx.x * blockDim.x + threadIdx.x) >> 5;
    int lane = threadIdx.x & 31;
    int total = BB * (NN + MM);
    if (warp >= total) return;
    const float* ptr;
    float* out;
    if (warp < BB * NN) {
        ptr = seq1 + (size_t)warp * DD;
        out = g_n1 + warp;
    } else {
        int w = warp - BB * NN;
        ptr = seq2 + (size_t)w * DD;
        out = g_n2 + w;
    }
    float s = 0.f;
    for (int k = lane * 4; k < DD; k += 32 * 4) {
        float4 v = *(const float4*)(ptr + k);
        s += v.x * v.x + v.y * v.y + v.z * v.z + v.w * v.w;
    }
#pragma unroll
    for (int o = 16; o > 0; o >>= 1) s += __shfl_down_sync(FULL, s, o);
    if (lane == 0) *out = s;
}

// ---------------------------------------------------------------------------
// Cost matrix: tiled fp32 GEMM  dot = seq2[m] . seq1[n], then sqrt epilogue.
// ---------------------------------------------------------------------------
#define TBM 64
#define TBN 64
#define TBK 16

__global__ void __launch_bounds__(256) cost_kernel(const float* __restrict__ seq1,
                                                   const float* __restrict__ seq2) {
    __shared__ float As[TBK][TBM + 4];
    __shared__ float Bs[TBK][TBN + 4];

    int b  = blockIdx.z;
    int m0 = blockIdx.y * TBM;
    int n0 = blockIdx.x * TBN;
    const float* A  = seq2 + ((size_t)b * MM + m0) * DD;
    const float* Bp = seq1 + ((size_t)b * NN + n0) * DD;

    int tid = threadIdx.x;
    int lr  = tid >> 2;
    int lc  = (tid & 3) * 4;
    int ty  = tid >> 4;
    int tx  = tid & 15;

    float acc[4][4] = {};

    for (int k0 = 0; k0 < DD; k0 += TBK) {
        float4 av = *(const float4*)(A  + (size_t)lr * DD + k0 + lc);
        float4 bv = *(const float4*)(Bp + (size_t)lr * DD + k0 + lc);
        __syncthreads();
        As[lc + 0][lr] = av.x; As[lc + 1][lr] = av.y;
        As[lc + 2][lr] = av.z; As[lc + 3][lr] = av.w;
        Bs[lc + 0][lr] = bv.x; Bs[lc + 1][lr] = bv.y;
        Bs[lc + 2][lr] = bv.z; Bs[lc + 3][lr] = bv.w;
        __syncthreads();
#pragma unroll
        for (int k = 0; k < TBK; k++) {
            float4 a  = *(const float4*)&As[k][ty * 4];
            float4 bb = *(const float4*)&Bs[k][tx * 4];
            float ar[4] = {a.x, a.y, a.z, a.w};
            float br[4] = {bb.x, bb.y, bb.z, bb.w};
#pragma unroll
            for (int im = 0; im < 4; im++)
#pragma unroll
                for (int in = 0; in < 4; in++)
                    acc[im][in] += ar[im] * br[in];
        }
    }

#pragma unroll
    for (int im = 0; im < 4; im++) {
        int m = m0 + ty * 4 + im;
        float nm = g_n2[b * MM + m];
#pragma unroll
        for (int in = 0; in < 4; in++) {
            int n = n0 + tx * 4 + in;
            float d2 = nm + g_n1[b * NN + n] - 2.0f * acc[im][in];
            g_cost[((size_t)b * MM + m) * NN + n] = sqrtf(fmaxf(d2, 0.0f));
        }
    }
}

// ---------------------------------------------------------------------------
// LAPJV (rectangular-safe): row reduction + greedy tight seeding +
// iterated augmenting row reduction (auction sweeps, v=0 base; v changes
// only on columns at the moment they get matched; matched columns never
// unmatch -> free columns keep v = 0, the rectangular-duality invariant) +
// exact Dijkstra augmentation for the remainder.
// One warp per batch; lane owns columns j-1 = 32*c + lane, c = 0..15.
// ---------------------------------------------------------------------------
#define MAXU64 0xFFFFFFFFFFFFFFFFULL
#define GUARD  1e-4f
#define ARR_SWEEPS 64

__device__ __forceinline__ unsigned long long dsort(double d) {
    long long x = __double_as_longlong(d);
    return (unsigned long long)(x ^ ((x >> 63) | 0x8000000000000000LL));
}
__device__ __forceinline__ double dunsort(unsigned long long u) {
    long long x = (long long)u;
    long long b = (x < 0) ? (x ^ 0x8000000000000000LL) : ~x;
    return __longlong_as_double(b);
}

__global__ void __launch_bounds__(32) jv_warp_kernel() {
    __shared__ double u[MM + 1];     // row potentials
    __shared__ double sarr[NN];      // D at marking time, per column
    __shared__ int    p[NN + 1];     // column -> assigned row (1-based), 0=free
    __shared__ int    way[NN + 1];
    __shared__ int    argcol[MM + 1];// row -> argmin column (1-based)
    __shared__ int    freelist[MM];

    int b = blockIdx.x;
    const float* cbase = g_cost + (size_t)b * MM * NN;
    int lane = threadIdx.x;

    for (int t = lane; t < NN + 1; t += 32) { p[t] = 0; way[t] = 0; }
    __syncwarp();

    // per-lane duals for owned columns (v = 0 base everywhere)
    double v[16];
#pragma unroll
    for (int c = 0; c < 16; c++) v[c] = 0.0;

    // ---- Phase A: row reduction  u[i] = min_j c[i][j], record argmin -----
    for (int i = 1; i <= MM; i++) {
        const float* crow = cbase + (size_t)(i - 1) * NN;
        float m = 3.0e38f;
        int bj = 0x7fffffff;
#pragma unroll
        for (int c = 0; c < 16; c++) {
            float f = __ldg(crow + c * 32 + lane);
            if (f < m) { m = f; bj = c * 32 + lane; }
        }
#pragma unroll
        for (int o = 16; o > 0; o >>= 1) {
            float om = __shfl_xor_sync(FULL, m, o);
            int obj = __shfl_xor_sync(FULL, bj, o);
            if (om < m || (om == m && obj < bj)) { m = om; bj = obj; }
        }
        if (lane == 0) { u[i] = (double)m; argcol[i] = bj + 1; }
    }
    __syncwarp();

    // ---- Phase B: greedy tight seeding (lane 0, serial) ------------------
    int numfree = 0;
    if (lane == 0) {
        for (int i = 1; i <= MM; i++) {
            int j = argcol[i];
            if (p[j] == 0) p[j] = i;       // tight: c - u - 0 == 0
            else           freelist[numfree++] = i;
        }
    }
    numfree = __shfl_sync(FULL, numfree, 0);
    __syncwarp();

    // ---- Phase B2: iterated augmenting row reduction (auction sweeps) ----
    // Gauss-Seidel auction with eps=0: each displacement strictly lowers the
    // contested column's v, diverting rows toward free columns over sweeps.
    // Sweep cost decays with the collision set; each resolved row deletes a
    // ~100us phase-C Dijkstra. v kept in per-lane registers; the single
    // column whose v changes is patched via the broadcast j1.
    for (int sweep = 0; sweep < ARR_SWEEPS && numfree > 0; sweep++) {
        int prv = numfree;
        int nf2 = 0;
        for (int k = 0; k < prv; k++) {
            int fr = freelist[k];
            const float* crow = cbase + (size_t)(fr - 1) * NN;
            unsigned long long m1 = MAXU64, m2 = MAXU64;
            int bj = 0x7fffffff;
#pragma unroll
            for (int c = 0; c < 16; c++) {
                float f = __ldg(crow + c * 32 + lane);
                double cur = (double)f - v[c];
                unsigned long long cs = dsort(cur);
                if (cs < m1) { m2 = m1; m1 = cs; bj = c * 32 + lane; }
                else if (cs < m2) m2 = cs;
            }
            // warp merge of (min1, argmin1, min2); index tie-break keeps
            // ALL lanes converged on the same bj even on exact fp64 ties.
#pragma unroll
            for (int o = 16; o > 0; o >>= 1) {
                unsigned long long om1 = __shfl_xor_sync(FULL, m1, o);
                unsigned long long om2 = __shfl_xor_sync(FULL, m2, o);
                int obj = __shfl_xor_sync(FULL, bj, o);
                bool take = (om1 < m1) || (om1 == m1 && obj < bj);
                unsigned long long ca = take ? om2 : m2;
                unsigned long long cb = take ? m1  : om1;
                if (take) { m1 = om1; bj = obj; }
                m2 = (cb < ca) ? cb : ca;
            }
            int j1 = bj + 1;                 // warp-uniform
            double u1 = dunsort(m1);
            double u2 = dunsort(m2);

            int i1 = p[j1];                  // ALL lanes read first...
            __syncwarp();                    // ...ordered before writes
            if (lane == 0) {
                u[fr] = u2;                  // tight (+feasible: others >= m2)
                p[j1] = fr;
            }
            // v[j1] -= (u2 - u1) on the owning lane's register copy
            if ((m1 < m2) && lane == (bj & 31)) v[bj >> 5] -= (u2 - u1);
            __syncwarp();
            if (i1) {                        // uniform across warp
                if (lane == 0) freelist[nf2] = i1;   // nf2 <= k: in-place safe
                nf2++;
                __syncwarp();
            }
        }
        numfree = nf2;
    }
    __syncwarp();

    float vf[16];
#pragma unroll
    for (int c = 0; c < 16; c++) vf[c] = (float)v[c];

    // ---- Phase C: exact Dijkstra augmentation (R3/R8-proven machinery) ---
    for (int t = 0; t < numfree; t++) {
        int i = freelist[t];

        unsigned long long msort[16];   // exact sorted-bits of minv (shifted)
        float minvf[16];                // fp32 approx of minv
        float thr[16];                  // filter threshold = minvf + vf + GUARD
#pragma unroll
        for (int c = 0; c < 16; c++) {
            msort[c] = MAXU64; minvf[c] = 3.0e38f; thr[c] = 3.0e38f;
        }
        unsigned long long lmin = MAXU64;
        int lidx = 0;
        unsigned umask = 0;
        double D = 0.0;
        int i0 = i;
        int j0 = 0;
        if (lane == 0) p[0] = i;
        __syncwarp();

        int jsel;
        double Df;

        while (true) {
            double h = D - u[i0];
            float hf = (float)h;
            const float* crow = cbase + (size_t)(i0 - 1) * NN;

            float f[16];
#pragma unroll
            for (int c = 0; c < 16; c++) f[c] = __ldg(crow + c * 32 + lane);

            // fp32 filter: 1 FADD + 1 FSETP per column
            unsigned pmask = 0;
#pragma unroll
            for (int c = 0; c < 16; c++)
                if (f[c] + hf < thr[c]) pmask |= 1u << c;

            // exact fp64 updates only for filtered columns
            while (pmask) {
                int c = __ffs(pmask) - 1;
                pmask &= pmask - 1;
                double cur = ((double)f[c] + h) - v[c];
                unsigned long long cs = dsort(cur);
                if (cs < msort[c]) {
                    msort[c] = cs;
                    minvf[c] = (float)cur;
                    thr[c]   = minvf[c] + vf[c] + GUARD;
                    way[c * 32 + lane + 1] = j0;
                    if (cs < lmin) { lmin = cs; lidx = c; }
                }
            }

            // warp argmin: exact value via 2x REDUX on sorted bits; winner
            // lane via ballot (consistent warp-uniform tie-break).
            unsigned hi = (unsigned)(lmin >> 32);
            unsigned mh = __reduce_min_sync(FULL, hi);
            unsigned lo = (hi == mh) ? (unsigned)lmin : 0xFFFFFFFFu;
            unsigned ml = __reduce_min_sync(FULL, lo);
            bool win = (hi == mh) && ((unsigned)lmin == ml);
            unsigned bal = __ballot_sync(FULL, win);
            int wl = __ffs(bal) - 1;                       // winner lane
            int widx = __shfl_sync(FULL, lidx, wl);
            unsigned long long wsv = __shfl_sync(FULL, lmin, wl);
            int j1 = widx * 32 + wl + 1;

            double Dnew = dunsort(wsv);
            D = Dnew;

            int pj1 = p[j1];           // broadcast LDS, warp-uniform
            if (pj1 == 0) { jsel = j1; Df = Dnew; break; }

            // mark j1 used (winner lane only) + rebuild its local min
            if (lane == wl) {
                umask |= 1u << widx;
                msort[widx] = MAXU64;
                minvf[widx] = -3.0e38f;
                thr[widx]   = -3.0e38f;    // filter can never pass again
                sarr[j1 - 1] = Dnew;
                lmin = MAXU64; lidx = 0;
#pragma unroll
                for (int c2 = 0; c2 < 16; c2++)
                    if (msort[c2] < lmin) { lmin = msort[c2]; lidx = c2; }
            }
            i0 = pj1;
            j0 = j1;
        }

        // deferred dual updates (p[] is pre-augmentation; only USED = matched
        // columns get v updates, so free columns keep v = 0 forever)
        unsigned um = umask;
        while (um) {
            int c = __ffs(um) - 1; um &= um - 1;
            int j = c * 32 + lane + 1;
            double adj = Df - sarr[j - 1];
            v[c] -= adj;
            vf[c] = (float)v[c];
            int r = p[j];              // distinct rows across used columns
            u[r] += adj;
        }
        if (lane == 0) u[i] += Df;
        __syncwarp();

        if (lane == 0) {
            int j0a = jsel;
            while (j0a) { int jp = way[j0a]; p[j0a] = p[jp]; j0a = jp; }
        }
        __syncwarp();
    }

    // perm: matched original rows ascending, then unmatched ascending
    int mbase = b * NN, mo = 0, uo = MM;
#pragma unroll
    for (int c = 0; c < 16; c++) {
        int j = c * 32 + lane + 1;
        bool mt = (p[j] != 0);
        unsigned bal = __ballot_sync(FULL, mt);
        unsigned ltm = (lane == 0) ? 0u : (FULL >> (32 - lane));
        int lt  = __popc(bal & ltm);
        int ltu = __popc((~bal) & ltm);
        if (mt)  g_perm[mbase + mo + lt]  = j - 1;
        if (!mt) g_perm[mbase + uo + ltu] = j - 1;
        mo += __popc(bal);
        uo += 32 - __popc(bal);
    }
}

// ---------------------------------------------------------------------------
// Gather: out[b][k] = seq1[b][perm[b][k]]
// ---------------------------------------------------------------------------
__global__ void gather_kernel(const float* __restrict__ seq1,
                              float* __restrict__ out) {
    int b   = blockIdx.y;
    int row = blockIdx.x;
    int src = g_perm[b * NN + row];
    const float4* s = (const float4*)(seq1 + ((size_t)b * NN + src) * DD);
    float4*       d = (float4*)(out  + ((size_t)b * NN + row) * DD);
    int k = threadIdx.x;
    d[k] = s[k];
}

// ---------------------------------------------------------------------------
extern "C" void kernel_launch(void* const* d_in, const int* in_sizes, int n_in,
                              void* d_out, int out_size) {
    const float* seq1 = (const float*)d_in[0];
    const float* seq2 = (const float*)d_in[1];
    float* out = (float*)d_out;

    int totalRows = BB * (NN + MM);
    norms_kernel<<<totalRows / 8, 256>>>(seq1, seq2);

    dim3 gc(NN / TBN, MM / TBM, BB);
    cost_kernel<<<gc, 256>>>(seq1, seq2);

    jv_warp_kernel<<<BB, 32>>>();

    gather_kernel<<<dim3(NN, BB), DD / 4>>>(seq1, out);
}